// round 15
// baseline (speedup 1.0000x reference)
#include <cuda_runtime.h>
#include <cuda_bf16.h>
#include <cstdint>

#define NB 32
#define WPB 8
#define THREADS (WPB * 32)

__device__ __forceinline__ float sqrt_approx(float x) {
    float r;
    asm("sqrt.approx.f32 %0, %1;" : "=f"(r) : "f"(x));   // sqrt.approx(+0)=+0
    return r;
}

__device__ __forceinline__ float fma_sat(float a, float b, float c) {
    float r;
    asm("fma.rn.sat.f32 %0, %1, %2, %3;" : "=f"(r) : "f"(a), "f"(b), "f"(c));
    return r;
}

__device__ __forceinline__ uint64_t policy_evict_last() {
    uint64_t p;
    asm("createpolicy.fractional.L2::evict_last.b64 %0, 1.0;" : "=l"(p));
    return p;
}

__device__ __forceinline__ void cp_async16_el(void* smem_dst, const float* gmem_src,
                                              uint64_t pol) {
    unsigned sa = (unsigned)__cvta_generic_to_shared(smem_dst);
    asm volatile("cp.async.cg.shared.global.L2::cache_hint [%0], [%1], 16, %2;\n"
                 :: "r"(sa), "l"(gmem_src), "l"(pol) : "memory");
}

__device__ __forceinline__ float ldg_evict_last(const float* p, uint64_t pol) {
    float v;
    asm("ld.global.L2::cache_hint.f32 %0, [%1], %2;" : "=f"(v) : "l"(p), "l"(pol));
    return v;
}

__global__ __launch_bounds__(THREADS, 6)
void BioTokenMucusSim_kernel(const float* __restrict__ h,
                             const float* __restrict__ W,
                             const float* __restrict__ stim,
                             float* __restrict__ h_out,
                             float* __restrict__ W_out,
                             int n_pairs)
{
    // per warp: 4KB unpadded W tile + padded h array + mbarrier  -> 6 blocks/SM
    __shared__ __align__(128) float wsh[WPB][NB * NB];
    __shared__ float4   hsh[WPB][35];      // idx(k) = k + (k>>3), max 34
    __shared__ uint64_t mbarsh[WPB];

    const int warp = threadIdx.x >> 5;
    const int lane = threadIdx.x & 31;
    const int qr = lane >> 3;              // row-in-group (update pass)
    const int qc = (lane & 7) * 4;         // col offset  (update pass)
    const int pair = blockIdx.x * WPB + warp;
    if (pair >= n_pairs) return;

    float*  ws = wsh[warp];
    float4* hs = hsh[warp];
    const uint32_t mbar = (uint32_t)__cvta_generic_to_shared(&mbarsh[warp]);
    const uint64_t pol = policy_evict_last();

    // ---- W tile: ONE bulk DMA copy (off the per-lane LSU path) ----
    if (lane == 0)
        asm volatile("mbarrier.init.shared.b64 [%0], %1;" :: "r"(mbar), "r"(1) : "memory");
    __syncwarp();
    if (lane == 0) {
        asm volatile("mbarrier.arrive.expect_tx.shared.b64 _, [%0], %1;"
                     :: "r"(mbar), "r"(NB * NB * 4) : "memory");
        const uint32_t dst = (uint32_t)__cvta_generic_to_shared(ws);
        asm volatile(
            "cp.async.bulk.shared::cluster.global.mbarrier::complete_tx::bytes.L2::cache_hint"
            " [%0], [%1], %2, [%3], %4;"
            :: "r"(dst), "l"(W + (size_t)pair * NB * NB), "r"(NB * NB * 4),
               "r"(mbar), "l"(pol) : "memory");
    }

    // ---- h: per-lane cp.async into padded array; stim via LDG ----
    const int hidx = lane + (lane >> 3);
    cp_async16_el(&hs[hidx], h + (size_t)pair * NB * 4 + lane * 4, pol);
    asm volatile("cp.async.commit_group;" ::: "memory");
    const float s = ldg_evict_last(stim + (size_t)pair * NB + lane, pol);
    asm volatile("cp.async.wait_group 0;" ::: "memory");

    // ---- wait for the W bulk copy (acquire orders subsequent LDS) ----
    {
        uint32_t done = 0;
        while (!done)
            asm volatile(
                "{\n\t.reg .pred p;\n\t"
                "mbarrier.try_wait.parity.acquire.cta.shared::cta.b64 p, [%1], 0;\n\t"
                "selp.b32 %0, 1, 0, p;\n\t}"
                : "=r"(done) : "r"(mbar) : "memory");
    }
    __syncwarp();                           // all lanes' h writes visible too

    ws[lane * NB + lane] = 0.0f;            // diag := 0 (matvec + update)
    const float4 hv = hs[hidx];
    __syncwarp();

    // ---- masked matvec: rotated column-groups keep unpadded rows conflict-free ----
    float ifx = 0.f, ify = 0.f, ifz = 0.f, ifw = 0.f, wsum = 0.f;
    #pragma unroll
    for (int t = 0; t < 8; ++t) {
        const int cg = (t + lane) & 7;                         // rotation
        const float4 w4 = *(const float4*)(ws + lane * NB + cg * 4);
        const int jb = cg * 4 + (cg >> 1);                     // padded idx base
        const float wq[4] = {w4.x, w4.y, w4.z, w4.w};
        #pragma unroll
        for (int e = 0; e < 4; ++e) {
            const float4 hj = hs[jb + e];
            ifx  = fmaf(wq[e], hj.x, ifx);
            ify  = fmaf(wq[e], hj.y, ify);
            ifz  = fmaf(wq[e], hj.z, ifz);
            ifw  = fmaf(wq[e], hj.w, ifw);
            wsum += wq[e];
        }
    }
    const float inv = 1.0f / (wsum + 1e-8f);
    const float En = ifx * inv, Pn = ify * inv, Gn = ifz * inv, Ln = ifw * inv;

    // ---- channel update ----
    const float E = hv.x, P = hv.y, G = hv.z, L = hv.w;
    const float E_new = fma_sat(-0.2f, G, fmaf(-0.4f, P, fmaf(0.3f, s, E)));
    const float P_new = fma_sat(-0.2f, E, fmaf(0.3f, Pn - P, fmaf(0.5f, s, P)));
    const float G_new = fma_sat(-0.3f, P, fmaf(0.2f, Gn - G,
                                fmaf(0.4f * E, 1.0f - P, G)));
    const float good  = 0.5f * En + 0.5f * Gn;
    const float L_new = fma_sat(-0.3f, P, fmaf(0.3f, Ln - L, fmaf(0.4f, good, L)));

    const float4 hn = make_float4(E_new, P_new, G_new, L_new);
    __stcs((float4*)(h_out + (size_t)pair * NB * 4) + lane, hn);

    __syncwarp();                            // matvec h reads done
    hs[hidx] = hn;                           // publish h_new
    __syncwarp();

    // ---- fused W-update + streaming store (diag implicit: wq=0, dist=0) ----
    float4 hj4[4];
    float  lj05[4];
    const int jb0 = qc + ((lane & 7) >> 1);  // padded idx of qc
    #pragma unroll
    for (int e = 0; e < 4; ++e) {
        hj4[e]  = hs[jb0 + e];
        lj05[e] = 0.05f * hj4[e].w;
    }

    float* Wo = W_out + (size_t)pair * (NB * NB);
    #pragma unroll
    for (int t = 0; t < 8; ++t) {
        const int r = t * 4 + qr;
        const float4 w  = *(const float4*)(ws + r * NB + qc);   // contiguous 512B
        const float4 hr = hs[r + (t >> 1)];                     // idx(r) = r + (r>>3)
        const float hr05 = 0.05f * hr.w;
        const float wq[4] = {w.x, w.y, w.z, w.w};
        float out[4];
        #pragma unroll
        for (int e = 0; e < 4; ++e) {
            const float dx = hr.x - hj4[e].x, dy = hr.y - hj4[e].y;
            const float dz = hr.z - hj4[e].z, dw = hr.w - hj4[e].w;
            float sq = dx * dx;
            sq = fmaf(dy, dy, sq);
            sq = fmaf(dz, dz, sq);
            sq = fmaf(dw, dw, sq);
            const float dist = sqrt_approx(sq);
            out[e] = fma_sat(hr05 + lj05[e], dist, 0.95f * wq[e]);
        }
        __stcs((float4*)(Wo + r * NB) + (lane & 7),
               make_float4(out[0], out[1], out[2], out[3]));
    }
}

extern "C" void kernel_launch(void* const* d_in, const int* in_sizes, int n_in,
                              void* d_out, int out_size) {
    const float* h    = (const float*)d_in[0];  // [B,S,32,4]
    const float* W    = (const float*)d_in[1];  // [B,S,32,32]
    const float* stim = (const float*)d_in[2];  // [B,S,32]

    const int n_pairs = in_sizes[2] / NB;       // B*S = 16384

    float* h_out = (float*)d_out;                       // h_new first
    float* W_out = (float*)d_out + (size_t)in_sizes[0]; // then W_new

    const int blocks = (n_pairs + WPB - 1) / WPB;       // 2048
    BioTokenMucusSim_kernel<<<blocks, THREADS>>>(h, W, stim, h_out, W_out, n_pairs);
}